// round 8
// baseline (speedup 1.0000x reference)
#include <cuda_runtime.h>
#include <cstdint>

// Problem constants
#define BSZ   2048
#define DIM   1024
#define DWM   512
#define WIN   256
#define NH    8
#define HD    64
#define QKV_LD 1536
#define ATT_SCALE 0.125f

// Scratch (device globals: allocation-free rule)
__device__ float g_qkv[(size_t)BSZ * QKV_LD];   // 12 MB
__device__ float g_att[(size_t)BSZ * DWM];      // 4 MB

// ---------------- bool dtype helpers ------------------------------------------
__device__ __forceinline__ int bool_mode(const unsigned char* valid)
{
    unsigned char b0 = valid[0], b1 = valid[1];
    return (b0 == 0) ? 2 : (b1 != 0 ? 0 : 1);   // 0=u8, 1=i32, 2=f32
}
__device__ __forceinline__ bool read_bool(const void* p, long idx, int mode)
{
    if (mode == 1) return ((const int*)p)[idx] != 0;
    if (mode == 2) return ((const float*)p)[idx] != 0.0f;
    return ((const unsigned char*)p)[idx] != 0;
}

// ---------------- tf32 helpers ------------------------------------------------
__device__ __forceinline__ uint32_t f2tf32(float f) {
    uint32_t u;
    asm("cvt.rna.tf32.f32 %0, %1;" : "=r"(u) : "f"(f));
    return u;
}
__device__ __forceinline__ void mma_tf32(float* d, const uint32_t* a, const uint32_t* b) {
    asm volatile(
        "mma.sync.aligned.m16n8k8.row.col.f32.tf32.tf32.f32 "
        "{%0,%1,%2,%3},{%4,%5,%6,%7},{%8,%9},{%0,%1,%2,%3};\n"
        : "+f"(d[0]), "+f"(d[1]), "+f"(d[2]), "+f"(d[3])
        : "r"(a[0]), "r"(a[1]), "r"(a[2]), "r"(a[3]), "r"(b[0]), "r"(b[1]));
}

// ===================== tf32 mma.sync GEMM (NT + bias), templated =============
// C[m,n] = sum_k A[m,k]*B[n,k] + bias[n]
// THREADS=256: CTA tile 128x128 (8 warps,  2m x 4n)
// THREADS=512: CTA tile 256x128 (16 warps, 4m x 4n)
// Warp tile always 64x32, K-tile 32, double-buffered XOR-swizzled smem.
#define BK 32
#define BN 128

template<int THREADS>
__device__ __forceinline__ void tc_gemm_body(
    const float* __restrict__ A, const float* __restrict__ Bw,
    const float* __restrict__ bias, float* __restrict__ C,
    int K, int ldc, int rowBase, int colB, int colC, int niter)
{
    constexpr int BMT   = THREADS / 2;          // 128 or 256
    constexpr int A_FL  = BMT * BK;             // floats in A tile
    constexpr int B_FL  = BN * BK;              // 4096
    constexpr int BUF   = A_FL + B_FL;
    constexpr int BI    = 1024 / THREADS * 1;   // B float4 iters: 4 or 2
    // A float4 iters: (BMT*BK/4)/THREADS = 4 for both configs

    extern __shared__ float smem[];
    const int tid  = threadIdx.x;
    const int lane = tid & 31;
    const int warp = tid >> 5;
    const int g    = lane >> 2;
    const int tg   = lane & 3;
    const int wm   = (warp >> 2) * 64;
    const int wn   = (warp & 3) * 32;

    const float* Abase = A  + (size_t)rowBase * K;
    const float* Bbase = Bw + (size_t)colB  * K;

    float acc[4][4][4];
    #pragma unroll
    for (int mt = 0; mt < 4; ++mt)
        #pragma unroll
        for (int nt = 0; nt < 4; ++nt)
            #pragma unroll
            for (int r = 0; r < 4; ++r) acc[mt][nt][r] = 0.f;

    float4 pa[4], pb[BI];

    // ---- prefetch + store tile 0 ----
    #pragma unroll
    for (int i = 0; i < 4; ++i) {
        int idx = tid + i * THREADS, row = idx >> 3, q = idx & 7;
        pa[i] = *(const float4*)(Abase + (size_t)row * K + (q << 2));
    }
    #pragma unroll
    for (int i = 0; i < BI; ++i) {
        int idx = tid + i * THREADS, row = idx >> 3, q = idx & 7;
        pb[i] = *(const float4*)(Bbase + (size_t)row * K + (q << 2));
    }
    {
        float* Abuf = smem;
        float* Bbuf = smem + A_FL;
        #pragma unroll
        for (int i = 0; i < 4; ++i) {
            int idx = tid + i * THREADS, row = idx >> 3, q = idx & 7;
            uint4 t;
            t.x = f2tf32(pa[i].x); t.y = f2tf32(pa[i].y);
            t.z = f2tf32(pa[i].z); t.w = f2tf32(pa[i].w);
            *(uint4*)(Abuf + row * BK + ((q ^ (row & 7)) << 2)) = t;
        }
        #pragma unroll
        for (int i = 0; i < BI; ++i) {
            int idx = tid + i * THREADS, row = idx >> 3, q = idx & 7;
            uint4 t;
            t.x = f2tf32(pb[i].x); t.y = f2tf32(pb[i].y);
            t.z = f2tf32(pb[i].z); t.w = f2tf32(pb[i].w);
            *(uint4*)(Bbuf + row * BK + ((q ^ (row & 7)) << 2)) = t;
        }
    }
    __syncthreads();

    for (int it = 0; it < niter; ++it) {
        const int buf = it & 1;
        if (it + 1 < niter) {
            const float* An = Abase + (it + 1) * BK;
            const float* Bn = Bbase + (it + 1) * BK;
            #pragma unroll
            for (int i = 0; i < 4; ++i) {
                int idx = tid + i * THREADS, row = idx >> 3, q = idx & 7;
                pa[i] = *(const float4*)(An + (size_t)row * K + (q << 2));
            }
            #pragma unroll
            for (int i = 0; i < BI; ++i) {
                int idx = tid + i * THREADS, row = idx >> 3, q = idx & 7;
                pb[i] = *(const float4*)(Bn + (size_t)row * K + (q << 2));
            }
        }
        {
            const uint32_t* Abuf = (const uint32_t*)(smem + buf * BUF);
            const uint32_t* Bbuf = Abuf + A_FL;
            #pragma unroll
            for (int ks = 0; ks < 4; ++ks) {
                uint32_t af[4][4], bf[4][2];
                const int g0 = ((2 * ks) ^ g) << 2;
                const int g1 = ((2 * ks + 1) ^ g) << 2;
                #pragma unroll
                for (int mt = 0; mt < 4; ++mt) {
                    int r0 = wm + mt * 16 + g;
                    int r1 = r0 + 8;
                    af[mt][0] = Abuf[r0 * BK + g0 + tg];
                    af[mt][1] = Abuf[r1 * BK + g0 + tg];
                    af[mt][2] = Abuf[r0 * BK + g1 + tg];
                    af[mt][3] = Abuf[r1 * BK + g1 + tg];
                }
                #pragma unroll
                for (int nt = 0; nt < 4; ++nt) {
                    int n = wn + nt * 8 + g;
                    bf[nt][0] = Bbuf[n * BK + g0 + tg];
                    bf[nt][1] = Bbuf[n * BK + g1 + tg];
                }
                #pragma unroll
                for (int mt = 0; mt < 4; ++mt)
                    #pragma unroll
                    for (int nt = 0; nt < 4; ++nt)
                        mma_tf32(acc[mt][nt], af[mt], bf[nt]);
            }
        }
        if (it + 1 < niter) {
            float* Abuf = smem + (buf ^ 1) * BUF;
            float* Bbuf = Abuf + A_FL;
            #pragma unroll
            for (int i = 0; i < 4; ++i) {
                int idx = tid + i * THREADS, row = idx >> 3, q = idx & 7;
                uint4 t;
                t.x = f2tf32(pa[i].x); t.y = f2tf32(pa[i].y);
                t.z = f2tf32(pa[i].z); t.w = f2tf32(pa[i].w);
                *(uint4*)(Abuf + row * BK + ((q ^ (row & 7)) << 2)) = t;
            }
            #pragma unroll
            for (int i = 0; i < BI; ++i) {
                int idx = tid + i * THREADS, row = idx >> 3, q = idx & 7;
                uint4 t;
                t.x = f2tf32(pb[i].x); t.y = f2tf32(pb[i].y);
                t.z = f2tf32(pb[i].z); t.w = f2tf32(pb[i].w);
                *(uint4*)(Bbuf + row * BK + ((q ^ (row & 7)) << 2)) = t;
            }
            __syncthreads();
        }
    }

    // ---- epilogue: C = acc + bias ----
    #pragma unroll
    for (int mt = 0; mt < 4; ++mt) {
        #pragma unroll
        for (int nt = 0; nt < 4; ++nt) {
            int r0  = rowBase + wm + mt * 16 + g;
            int col = wn + nt * 8 + tg * 2;
            float b0 = bias[colB + col], b1 = bias[colB + col + 1];
            float2 v0 = make_float2(acc[mt][nt][0] + b0, acc[mt][nt][1] + b1);
            float2 v1 = make_float2(acc[mt][nt][2] + b0, acc[mt][nt][3] + b1);
            *(float2*)(C + (size_t)r0 * ldc + colC + col) = v0;
            *(float2*)(C + (size_t)(r0 + 8) * ldc + colC + col) = v1;
        }
    }
}

#define QKV_SMEM ((256 * BK + BN * BK) * 4 * 2)   // 98304
#define OUT_SMEM ((128 * BK + BN * BK) * 4 * 2)   // 65536

__global__ __launch_bounds__(512, 1) void qkv_gemm_tc(
    const float* __restrict__ x,
    const float* __restrict__ Wq, const float* __restrict__ bq,
    const float* __restrict__ Wk, const float* __restrict__ bk,
    const float* __restrict__ Wv, const float* __restrict__ bv)
{
    const int y  = blockIdx.y;         // 0..11
    const int z  = y >> 2;             // which weight
    const int nc = (y & 3) * BN;       // col block within D_WM
    const float* Bw = (z == 0) ? Wq : (z == 1) ? Wk : Wv;
    const float* bi = (z == 0) ? bq : (z == 1) ? bk : bv;
    tc_gemm_body<512>(x, Bw, bi, g_qkv, DIM, QKV_LD,
                      blockIdx.x * 256, nc, z * DWM + nc, DIM / BK);
}

__global__ __launch_bounds__(256) void out_gemm_tc(
    const float* __restrict__ Wo, const float* __restrict__ bo,
    float* __restrict__ y)
{
    tc_gemm_body<256>(g_att, Wo, bo, y, DWM, DIM,
                      blockIdx.x * 128, blockIdx.y * BN, blockIdx.y * BN, DWM / BK);
}

// ---------------- Attention kernel (R4-proven form): one CTA per batch row ---
__global__ __launch_bounds__(256) void attn_kernel(
    const float* __restrict__ wmK, const float* __restrict__ wmV,
    const void* __restrict__ validIn,
    const void* __restrict__ resetIn,
    const int* __restrict__ ptrIn)
{
    __shared__ float q_s[DWM];
    __shared__ float att_s[NH][WIN];
    __shared__ unsigned char valid_s[WIN];

    const int b    = blockIdx.x;
    const int tid  = threadIdx.x;   // 256
    const int lane = tid & 31;
    const int warp = tid >> 5;      // 8 warps == 8 heads

    const int mode = bool_mode((const unsigned char*)validIn);
    const bool rs = read_bool(resetIn, b, mode);
    const int  p  = rs ? 0 : ptrIn[b];

    const float* qrow  = g_qkv + (size_t)b * QKV_LD;
    const float* knew  = qrow + DWM;
    const float* vnew  = qrow + 2 * DWM;
    const float* Kbase = wmK + (size_t)b * WIN * DWM;
    const float* Vbase = wmV + (size_t)b * WIN * DWM;

    for (int i = tid; i < DWM; i += 256) q_s[i] = qrow[i];
    if (tid < WIN)
        valid_s[tid] = read_bool(validIn, (size_t)b * WIN + tid, mode) ? 1 : 0;
    __syncthreads();

    const float NEG_INF = __int_as_float(0xff800000);

    // ---- phase 1: logits (uniform over stored K; slot p patched after) ----
    {
        const int h = warp;
        float2 qv = *(const float2*)(q_s + h * HD + lane * 2);
        const float2* kp = (const float2*)(Kbase + h * HD + lane * 2);
        for (int w0 = 0; w0 < WIN; w0 += 8) {
            float s[8];
            #pragma unroll
            for (int u = 0; u < 8; ++u) {
                float2 kv = __ldcs(kp + (size_t)(w0 + u) * (DWM / 2));
                s[u] = kv.x * qv.x + kv.y * qv.y;
            }
            #pragma unroll
            for (int u = 0; u < 8; ++u) {
                #pragma unroll
                for (int o = 16; o > 0; o >>= 1)
                    s[u] += __shfl_xor_sync(0xffffffffu, s[u], o);
            }
            if (lane == 0) {
                #pragma unroll
                for (int u = 0; u < 8; ++u) {
                    int w = w0 + u;
                    bool val = !rs && (valid_s[w] != 0);
                    att_s[h][w] = val ? s[u] * ATT_SCALE : NEG_INF;
                }
            }
        }
        // substitute fresh k at slot p (always valid)
        {
            float2 kv = *(const float2*)(knew + h * HD + lane * 2);
            float s = kv.x * qv.x + kv.y * qv.y;
            #pragma unroll
            for (int o = 16; o > 0; o >>= 1)
                s += __shfl_xor_sync(0xffffffffu, s, o);
            if (lane == 0) att_s[h][p] = s * ATT_SCALE;
        }
    }
    __syncthreads();

    // ---- phase 2: per-head softmax (warp h) ----
    {
        const int h = warp;
        float e[8];
        float m = NEG_INF;
        #pragma unroll
        for (int j = 0; j < 8; ++j) {
            e[j] = att_s[h][lane + 32 * j];
            m = fmaxf(m, e[j]);
        }
        #pragma unroll
        for (int o = 16; o > 0; o >>= 1)
            m = fmaxf(m, __shfl_xor_sync(0xffffffffu, m, o));
        float sum = 0.f;
        #pragma unroll
        for (int j = 0; j < 8; ++j) {
            e[j] = __expf(e[j] - m);
            sum += e[j];
        }
        #pragma unroll
        for (int o = 16; o > 0; o >>= 1)
            sum += __shfl_xor_sync(0xffffffffu, sum, o);
        float inv = (sum > 0.f) ? (1.0f / sum) : 0.f;
        #pragma unroll
        for (int j = 0; j < 8; ++j)
            att_s[h][lane + 32 * j] = e[j] * inv;
    }
    __syncthreads();

    // ---- phase 3: AV, uniform over stored V; correction for slot p ----
    {
        const int d = tid * 2;
        const int h = tid >> 5;
        float ax = 0.f, ay = 0.f;
        const float2* vp = (const float2*)(Vbase + d);
        for (int w0 = 0; w0 < WIN; w0 += 8) {
            float2 vv[8];
            #pragma unroll
            for (int u = 0; u < 8; ++u)
                vv[u] = __ldcs(vp + (size_t)(w0 + u) * (DWM / 2));
            #pragma unroll
            for (int u = 0; u < 8; ++u) {
                float pw = att_s[h][w0 + u];
                ax = fmaf(pw, vv[u].x, ax);
                ay = fmaf(pw, vv[u].y, ay);
            }
        }
        {
            float2 vold = *(const float2*)(Vbase + (size_t)p * DWM + d);
            float2 vn   = *(const float2*)(vnew + d);
            float pw = att_s[h][p];
            ax = fmaf(pw, vn.x - vold.x, ax);
            ay = fmaf(pw, vn.y - vold.y, ay);
        }
        *(float2*)(g_att + (size_t)b * DWM + d) = make_float2(ax, ay);
    }
}

// ---------------- launcher ---------------------------------------------------
extern "C" void kernel_launch(void* const* d_in, const int* in_sizes, int n_in,
                              void* d_out, int out_size)
{
    const float* x     = (const float*)d_in[0];
    const void*  reset = d_in[1];
    const float* wmK   = (const float*)d_in[2];
    const float* wmV   = (const float*)d_in[3];
    const void*  valid = d_in[4];
    const int*   ptr   = (const int*)d_in[5];
    const float* Wq    = (const float*)d_in[6];
    const float* bq    = (const float*)d_in[7];
    const float* Wk    = (const float*)d_in[8];
    const float* bk    = (const float*)d_in[9];
    const float* Wv    = (const float*)d_in[10];
    const float* bv    = (const float*)d_in[11];
    const float* Wo    = (const float*)d_in[12];
    const float* bo    = (const float*)d_in[13];
    float*       y     = (float*)d_out;

    // opt-in dynamic smem (host attribute set; idempotent)
    cudaFuncSetAttribute(qkv_gemm_tc, cudaFuncAttributeMaxDynamicSharedMemorySize, QKV_SMEM);
    cudaFuncSetAttribute(out_gemm_tc, cudaFuncAttributeMaxDynamicSharedMemorySize, OUT_SMEM);

    dim3 gQKV(BSZ / 256, 12);           // 8 x 12 = 96 CTAs -> one wave
    qkv_gemm_tc<<<gQKV, 512, QKV_SMEM>>>(x, Wq, bq, Wk, bk, Wv, bv);

    attn_kernel<<<BSZ, 256>>>(wmK, wmV, valid, reset, ptr);

    dim3 gOut(BSZ / 128, DIM / BN);     // 16 x 8 = 128 CTAs -> one wave
    out_gemm_tc<<<gOut, 256, OUT_SMEM>>>(Wo, bo, y);
}

// round 10
// speedup vs baseline: 1.8759x; 1.8759x over previous
#include <cuda_runtime.h>
#include <cstdint>

// Problem constants
#define BSZ   2048
#define DIM   1024
#define DWM   512
#define WIN   256
#define NH    8
#define HD    64
#define QKV_LD 1536
#define ATT_SCALE 0.125f

// Scratch (device globals: allocation-free rule)
__device__ float g_qkv[(size_t)BSZ * QKV_LD];   // 12 MB
__device__ float g_att[(size_t)BSZ * DWM];      // 4 MB

// ---------------- bool dtype helpers ------------------------------------------
__device__ __forceinline__ int bool_mode(const unsigned char* valid)
{
    unsigned char b0 = valid[0], b1 = valid[1];
    return (b0 == 0) ? 2 : (b1 != 0 ? 0 : 1);   // 0=u8, 1=i32, 2=f32
}
__device__ __forceinline__ bool read_bool(const void* p, long idx, int mode)
{
    if (mode == 1) return ((const int*)p)[idx] != 0;
    if (mode == 2) return ((const float*)p)[idx] != 0.0f;
    return ((const unsigned char*)p)[idx] != 0;
}

// ---------------- tf32 helpers ------------------------------------------------
__device__ __forceinline__ uint32_t f2tf32(float f) {
    uint32_t u;
    asm("cvt.rna.tf32.f32 %0, %1;" : "=r"(u) : "f"(f));
    return u;
}
__device__ __forceinline__ void mma_tf32(float* d, const uint32_t* a, const uint32_t* b) {
    asm volatile(
        "mma.sync.aligned.m16n8k8.row.col.f32.tf32.tf32.f32 "
        "{%0,%1,%2,%3},{%4,%5,%6,%7},{%8,%9},{%0,%1,%2,%3};\n"
        : "+f"(d[0]), "+f"(d[1]), "+f"(d[2]), "+f"(d[3])
        : "r"(a[0]), "r"(a[1]), "r"(a[2]), "r"(a[3]), "r"(b[0]), "r"(b[1]));
}

// ===================== tf32 mma.sync GEMM (NT + bias) =========================
// C[m,n] = sum_k A[m,k]*B[n,k] + bias[n]
// CTA tile 128x128, K-tile 32, 256 threads = 8 warps (2m x 4n), warp tile 64x32.
#define BM 128
#define BN 128
#define BK 32
#define A_FLOATS (BM * BK)               // 4096
#define B_FLOATS (BN * BK)               // 4096
#define BUF_FLOATS (A_FLOATS + B_FLOATS) // 8192
#define TCSM_BYTES (2 * BUF_FLOATS * 4)  // 65536 (opt-in)

__device__ __forceinline__ void tc_gemm_body(
    const float* __restrict__ A, const float* __restrict__ Bw,
    const float* __restrict__ bias, float* __restrict__ C,
    int K, int ldc, int rowBase, int colB, int colC, int niter)
{
    extern __shared__ float smem[];
    const int tid  = threadIdx.x;
    const int lane = tid & 31;
    const int warp = tid >> 5;
    const int g    = lane >> 2;          // 0..7
    const int tg   = lane & 3;           // 0..3
    const int wm   = (warp >> 2) * 64;   // 0,64
    const int wn   = (warp & 3) * 32;    // 0,32,64,96

    const float* Abase = A  + (size_t)rowBase * K;
    const float* Bbase = Bw + (size_t)colB  * K;

    float acc[4][4][4];
    #pragma unroll
    for (int mt = 0; mt < 4; ++mt)
        #pragma unroll
        for (int nt = 0; nt < 4; ++nt)
            #pragma unroll
            for (int r = 0; r < 4; ++r) acc[mt][nt][r] = 0.f;

    float4 pa[4], pb[4];

    // ---- prefetch + store tile 0 ----
    #pragma unroll
    for (int i = 0; i < 4; ++i) {
        int idx = tid + (i << 8), row = idx >> 3, q = idx & 7;
        pa[i] = *(const float4*)(Abase + (size_t)row * K + (q << 2));
        pb[i] = *(const float4*)(Bbase + (size_t)row * K + (q << 2));
    }
    {
        float* Abuf = smem;
        float* Bbuf = smem + A_FLOATS;
        #pragma unroll
        for (int i = 0; i < 4; ++i) {
            int idx = tid + (i << 8), row = idx >> 3, q = idx & 7;
            uint4 ta, tb;
            ta.x = f2tf32(pa[i].x); ta.y = f2tf32(pa[i].y);
            ta.z = f2tf32(pa[i].z); ta.w = f2tf32(pa[i].w);
            tb.x = f2tf32(pb[i].x); tb.y = f2tf32(pb[i].y);
            tb.z = f2tf32(pb[i].z); tb.w = f2tf32(pb[i].w);
            int soff = row * BK + ((q ^ (row & 7)) << 2);
            *(uint4*)(Abuf + soff) = ta;
            *(uint4*)(Bbuf + soff) = tb;
        }
    }
    __syncthreads();

    for (int it = 0; it < niter; ++it) {
        const int buf = it & 1;
        if (it + 1 < niter) {
            const float* An = Abase + (it + 1) * BK;
            const float* Bn = Bbase + (it + 1) * BK;
            #pragma unroll
            for (int i = 0; i < 4; ++i) {
                int idx = tid + (i << 8), row = idx >> 3, q = idx & 7;
                pa[i] = *(const float4*)(An + (size_t)row * K + (q << 2));
                pb[i] = *(const float4*)(Bn + (size_t)row * K + (q << 2));
            }
        }
        {
            const uint32_t* Abuf = (const uint32_t*)(smem + buf * BUF_FLOATS);
            const uint32_t* Bbuf = Abuf + A_FLOATS;
            #pragma unroll
            for (int ks = 0; ks < 4; ++ks) {
                uint32_t af[4][4], bf[4][2];
                const int g0 = ((2 * ks) ^ g) << 2;
                const int g1 = ((2 * ks + 1) ^ g) << 2;
                #pragma unroll
                for (int mt = 0; mt < 4; ++mt) {
                    int r0 = wm + mt * 16 + g;
                    int r1 = r0 + 8;
                    af[mt][0] = Abuf[r0 * BK + g0 + tg];
                    af[mt][1] = Abuf[r1 * BK + g0 + tg];
                    af[mt][2] = Abuf[r0 * BK + g1 + tg];
                    af[mt][3] = Abuf[r1 * BK + g1 + tg];
                }
                #pragma unroll
                for (int nt = 0; nt < 4; ++nt) {
                    int n = wn + nt * 8 + g;
                    bf[nt][0] = Bbuf[n * BK + g0 + tg];
                    bf[nt][1] = Bbuf[n * BK + g1 + tg];
                }
                #pragma unroll
                for (int mt = 0; mt < 4; ++mt)
                    #pragma unroll
                    for (int nt = 0; nt < 4; ++nt)
                        mma_tf32(acc[mt][nt], af[mt], bf[nt]);
            }
        }
        if (it + 1 < niter) {
            float* Abuf = smem + (buf ^ 1) * BUF_FLOATS;
            float* Bbuf = Abuf + A_FLOATS;
            #pragma unroll
            for (int i = 0; i < 4; ++i) {
                int idx = tid + (i << 8), row = idx >> 3, q = idx & 7;
                uint4 ta, tb;
                ta.x = f2tf32(pa[i].x); ta.y = f2tf32(pa[i].y);
                ta.z = f2tf32(pa[i].z); ta.w = f2tf32(pa[i].w);
                tb.x = f2tf32(pb[i].x); tb.y = f2tf32(pb[i].y);
                tb.z = f2tf32(pb[i].z); tb.w = f2tf32(pb[i].w);
                int soff = row * BK + ((q ^ (row & 7)) << 2);
                *(uint4*)(Abuf + soff) = ta;
                *(uint4*)(Bbuf + soff) = tb;
            }
            __syncthreads();
        }
    }

    // ---- epilogue: C = acc + bias ----
    #pragma unroll
    for (int mt = 0; mt < 4; ++mt) {
        #pragma unroll
        for (int nt = 0; nt < 4; ++nt) {
            int r0  = rowBase + wm + mt * 16 + g;
            int col = wn + nt * 8 + tg * 2;
            float b0 = bias[colB + col], b1 = bias[colB + col + 1];
            float2 v0 = make_float2(acc[mt][nt][0] + b0, acc[mt][nt][1] + b1);
            float2 v1 = make_float2(acc[mt][nt][2] + b0, acc[mt][nt][3] + b1);
            *(float2*)(C + (size_t)r0 * ldc + colC + col) = v0;
            *(float2*)(C + (size_t)(r0 + 8) * ldc + colC + col) = v1;
        }
    }
}

__global__ __launch_bounds__(256) void qkv_gemm_tc(
    const float* __restrict__ x,
    const float* __restrict__ Wq, const float* __restrict__ bq,
    const float* __restrict__ Wk, const float* __restrict__ bk,
    const float* __restrict__ Wv, const float* __restrict__ bv)
{
    const int y  = blockIdx.y;         // 0..11
    const int z  = y >> 2;             // which weight
    const int nc = (y & 3) * BN;       // col block within D_WM
    const float* Bw = (z == 0) ? Wq : (z == 1) ? Wk : Wv;
    const float* bi = (z == 0) ? bq : (z == 1) ? bk : bv;
    tc_gemm_body(x, Bw, bi, g_qkv, DIM, QKV_LD,
                 blockIdx.x * BM, nc, z * DWM + nc, DIM / BK);
}

__global__ __launch_bounds__(256) void out_gemm_tc(
    const float* __restrict__ Wo, const float* __restrict__ bo,
    float* __restrict__ y)
{
    tc_gemm_body(g_att, Wo, bo, y, DWM, DIM,
                 blockIdx.x * BM, blockIdx.y * BN, blockIdx.y * BN, DWM / BK);
}

// ---------------- Attention kernel: one CTA per batch row --------------------
// Reset rows: all slots invalidated, only freshly-written slot p valid
// -> softmax over one element -> out = v_new exactly. Early exit, no K/V reads.
__global__ __launch_bounds__(256) void attn_kernel(
    const float* __restrict__ wmK, const float* __restrict__ wmV,
    const void* __restrict__ validIn,
    const void* __restrict__ resetIn,
    const int* __restrict__ ptrIn)
{
    __shared__ float q_s[DWM];
    __shared__ float att_s[NH][WIN];
    __shared__ unsigned char valid_s[WIN];

    const int b    = blockIdx.x;
    const int tid  = threadIdx.x;   // 256
    const int lane = tid & 31;
    const int warp = tid >> 5;      // 8 warps == 8 heads

    const int mode = bool_mode((const unsigned char*)validIn);
    const bool rs = read_bool(resetIn, b, mode);

    const float* qrow  = g_qkv + (size_t)b * QKV_LD;
    const float* knew  = qrow + DWM;
    const float* vnew  = qrow + 2 * DWM;

    if (rs) {
        // out = v_new (attn weight 1 at the single valid slot)
        float2 v0 = *(const float2*)(vnew + tid * 2);
        *(float2*)(g_att + (size_t)b * DWM + tid * 2) = v0;
        return;
    }

    const int p = ptrIn[b];
    const float* Kbase = wmK + (size_t)b * WIN * DWM;
    const float* Vbase = wmV + (size_t)b * WIN * DWM;

    for (int i = tid; i < DWM; i += 256) q_s[i] = qrow[i];
    if (tid < WIN)
        valid_s[tid] = read_bool(validIn, (size_t)b * WIN + tid, mode) ? 1 : 0;
    __syncthreads();

    const float NEG_INF = __int_as_float(0xff800000);

    // ---- phase 1: logits (uniform over stored K; slot p patched after) ----
    {
        const int h = warp;
        float2 qv = *(const float2*)(q_s + h * HD + lane * 2);
        const float2* kp = (const float2*)(Kbase + h * HD + lane * 2);
        for (int w0 = 0; w0 < WIN; w0 += 8) {
            float s[8];
            #pragma unroll
            for (int u = 0; u < 8; ++u) {
                float2 kv = __ldcs(kp + (size_t)(w0 + u) * (DWM / 2));
                s[u] = kv.x * qv.x + kv.y * qv.y;
            }
            #pragma unroll
            for (int u = 0; u < 8; ++u) {
                #pragma unroll
                for (int o = 16; o > 0; o >>= 1)
                    s[u] += __shfl_xor_sync(0xffffffffu, s[u], o);
            }
            if (lane == 0) {
                #pragma unroll
                for (int u = 0; u < 8; ++u) {
                    int w = w0 + u;
                    bool val = (valid_s[w] != 0);
                    att_s[h][w] = val ? s[u] * ATT_SCALE : NEG_INF;
                }
            }
        }
        // substitute fresh k at slot p (always valid)
        {
            float2 kv = *(const float2*)(knew + h * HD + lane * 2);
            float s = kv.x * qv.x + kv.y * qv.y;
            #pragma unroll
            for (int o = 16; o > 0; o >>= 1)
                s += __shfl_xor_sync(0xffffffffu, s, o);
            if (lane == 0) att_s[h][p] = s * ATT_SCALE;
        }
    }
    __syncthreads();

    // ---- phase 2: per-head softmax (warp h) ----
    {
        const int h = warp;
        float e[8];
        float m = NEG_INF;
        #pragma unroll
        for (int j = 0; j < 8; ++j) {
            e[j] = att_s[h][lane + 32 * j];
            m = fmaxf(m, e[j]);
        }
        #pragma unroll
        for (int o = 16; o > 0; o >>= 1)
            m = fmaxf(m, __shfl_xor_sync(0xffffffffu, m, o));
        float sum = 0.f;
        #pragma unroll
        for (int j = 0; j < 8; ++j) {
            e[j] = __expf(e[j] - m);
            sum += e[j];
        }
        #pragma unroll
        for (int o = 16; o > 0; o >>= 1)
            sum += __shfl_xor_sync(0xffffffffu, sum, o);
        float inv = (sum > 0.f) ? (1.0f / sum) : 0.f;
        #pragma unroll
        for (int j = 0; j < 8; ++j)
            att_s[h][lane + 32 * j] = e[j] * inv;
    }
    __syncthreads();

    // ---- phase 3: AV, uniform over stored V; correction for slot p ----
    {
        const int d = tid * 2;
        const int h = tid >> 5;
        float ax = 0.f, ay = 0.f;
        const float2* vp = (const float2*)(Vbase + d);
        for (int w0 = 0; w0 < WIN; w0 += 8) {
            float2 vv[8];
            #pragma unroll
            for (int u = 0; u < 8; ++u)
                vv[u] = __ldcs(vp + (size_t)(w0 + u) * (DWM / 2));
            #pragma unroll
            for (int u = 0; u < 8; ++u) {
                float pw = att_s[h][w0 + u];
                ax = fmaf(pw, vv[u].x, ax);
                ay = fmaf(pw, vv[u].y, ay);
            }
        }
        {
            float2 vold = *(const float2*)(Vbase + (size_t)p * DWM + d);
            float2 vn   = *(const float2*)(vnew + d);
            float pw = att_s[h][p];
            ax = fmaf(pw, vn.x - vold.x, ax);
            ay = fmaf(pw, vn.y - vold.y, ay);
        }
        *(float2*)(g_att + (size_t)b * DWM + d) = make_float2(ax, ay);
    }
}

// ---------------- launcher ---------------------------------------------------
extern "C" void kernel_launch(void* const* d_in, const int* in_sizes, int n_in,
                              void* d_out, int out_size)
{
    const float* x     = (const float*)d_in[0];
    const void*  reset = d_in[1];
    const float* wmK   = (const float*)d_in[2];
    const float* wmV   = (const float*)d_in[3];
    const void*  valid = d_in[4];
    const int*   ptr   = (const int*)d_in[5];
    const float* Wq    = (const float*)d_in[6];
    const float* bq    = (const float*)d_in[7];
    const float* Wk    = (const float*)d_in[8];
    const float* bk    = (const float*)d_in[9];
    const float* Wv    = (const float*)d_in[10];
    const float* bv    = (const float*)d_in[11];
    const float* Wo    = (const float*)d_in[12];
    const float* bo    = (const float*)d_in[13];
    float*       y     = (float*)d_out;

    // opt-in to 64 KB dynamic smem (host attribute set; idempotent)
    cudaFuncSetAttribute(qkv_gemm_tc, cudaFuncAttributeMaxDynamicSharedMemorySize, TCSM_BYTES);
    cudaFuncSetAttribute(out_gemm_tc, cudaFuncAttributeMaxDynamicSharedMemorySize, TCSM_BYTES);

    dim3 gQKV(BSZ / BM, 12);            // 16 x 12 = 192 CTAs
    qkv_gemm_tc<<<gQKV, 256, TCSM_BYTES>>>(x, Wq, bq, Wk, bk, Wv, bv);

    attn_kernel<<<BSZ, 256>>>(wmK, wmV, valid, reset, ptr);

    dim3 gOut(BSZ / BM, DIM / BN);      // 16 x 8 = 128 CTAs
    out_gemm_tc<<<gOut, 256, TCSM_BYTES>>>(Wo, bo, y);
}

// round 11
// speedup vs baseline: 2.1447x; 1.1433x over previous
#include <cuda_runtime.h>
#include <cstdint>

// Problem constants
#define BSZ   2048
#define DIM   1024
#define DWM   512
#define WIN   256
#define NH    8
#define HD    64
#define QKV_LD 1536
#define ATT_SCALE 0.125f

// Scratch (device globals: allocation-free rule)
__device__ float g_qkv[(size_t)BSZ * QKV_LD];   // 12 MB
__device__ float g_att[(size_t)BSZ * DWM];      // 4 MB
__device__ int   g_rows[BSZ];                   // compacted non-reset row ids
__device__ int   g_nrows;                       // count of non-reset rows

// ---------------- bool dtype helpers ------------------------------------------
__device__ __forceinline__ int bool_mode(const unsigned char* valid)
{
    unsigned char b0 = valid[0], b1 = valid[1];
    return (b0 == 0) ? 2 : (b1 != 0 ? 0 : 1);   // 0=u8, 1=i32, 2=f32
}
__device__ __forceinline__ bool read_bool(const void* p, long idx, int mode)
{
    if (mode == 1) return ((const int*)p)[idx] != 0;
    if (mode == 2) return ((const float*)p)[idx] != 0.0f;
    return ((const unsigned char*)p)[idx] != 0;
}

// ---------------- compaction: non-reset row list (1 CTA, 1024 threads) --------
__global__ void compact_kernel(const void* __restrict__ resetIn,
                               const void* __restrict__ validIn)
{
    __shared__ int cnt_s[1024];
    const int tid = threadIdx.x;
    const int mode = bool_mode((const unsigned char*)validIn);

    const bool a = !read_bool(resetIn, 2 * tid, mode);
    const bool c = !read_bool(resetIn, 2 * tid + 1, mode);
    const int cnt = (int)a + (int)c;
    cnt_s[tid] = cnt;
    __syncthreads();
    // Hillis-Steele inclusive scan over 1024
    for (int off = 1; off < 1024; off <<= 1) {
        int add = (tid >= off) ? cnt_s[tid - off] : 0;
        int v   = cnt_s[tid];
        __syncthreads();
        cnt_s[tid] = v + add;
        __syncthreads();
    }
    int pos = cnt_s[tid] - cnt;   // exclusive prefix
    if (a) g_rows[pos++] = 2 * tid;
    if (c) g_rows[pos]   = 2 * tid + 1;
    if (tid == 1023) g_nrows = cnt_s[1023];
}

// ---------------- tf32 helpers ------------------------------------------------
__device__ __forceinline__ uint32_t f2tf32(float f) {
    uint32_t u;
    asm("cvt.rna.tf32.f32 %0, %1;" : "=r"(u) : "f"(f));
    return u;
}
__device__ __forceinline__ void mma_tf32(float* d, const uint32_t* a, const uint32_t* b) {
    asm volatile(
        "mma.sync.aligned.m16n8k8.row.col.f32.tf32.tf32.f32 "
        "{%0,%1,%2,%3},{%4,%5,%6,%7},{%8,%9},{%0,%1,%2,%3};\n"
        : "+f"(d[0]), "+f"(d[1]), "+f"(d[2]), "+f"(d[3])
        : "r"(a[0]), "r"(a[1]), "r"(a[2]), "r"(a[3]), "r"(b[0]), "r"(b[1]));
}

// ===================== tf32 mma.sync GEMM (NT + bias) =========================
// C[m,n] = sum_k A[m,k]*B[n,k] + bias[n]
// CTA tile 128x128, K-tile 32, 256 threads = 8 warps (2m x 4n), warp tile 64x32.
// GATHER=true: A rows / C rows are indirected through g_rows (masked past nrows).
#define BM 128
#define BN 128
#define BK 32
#define A_FLOATS (BM * BK)               // 4096
#define B_FLOATS (BN * BK)               // 4096
#define BUF_FLOATS (A_FLOATS + B_FLOATS) // 8192
#define TCSM_BYTES (2 * BUF_FLOATS * 4)  // 65536 (opt-in)

template<bool GATHER>
__device__ __forceinline__ void tc_gemm_body(
    const float* __restrict__ A, const float* __restrict__ Bw,
    const float* __restrict__ bias, float* __restrict__ C,
    int K, int ldc, int rowBase, int colB, int colC, int niter, int nrows)
{
    extern __shared__ float smem[];
    __shared__ int ridx_s[BM];

    const int tid  = threadIdx.x;
    const int lane = tid & 31;
    const int warp = tid >> 5;
    const int g    = lane >> 2;          // 0..7
    const int tg   = lane & 3;           // 0..3
    const int wm   = (warp >> 2) * 64;   // 0,64
    const int wn   = (warp & 3) * 32;    // 0,32,64,96

    if (GATHER) {
        if (tid < BM) {
            int rr = rowBase + tid;
            ridx_s[tid] = (rr < nrows) ? g_rows[rr] : 0;  // dummy row 0 when padded
        }
        __syncthreads();
    }

    const float* Bbase = Bw + (size_t)colB * K;

    float acc[4][4][4];
    #pragma unroll
    for (int mt = 0; mt < 4; ++mt)
        #pragma unroll
        for (int nt = 0; nt < 4; ++nt)
            #pragma unroll
            for (int r = 0; r < 4; ++r) acc[mt][nt][r] = 0.f;

    float4 pa[4], pb[4];

    // helper for A row pointer
    auto arow = [&](int row) -> const float* {
        int rr = GATHER ? ridx_s[row] : (rowBase + row);
        return A + (size_t)rr * K;
    };

    // ---- prefetch + store tile 0 ----
    #pragma unroll
    for (int i = 0; i < 4; ++i) {
        int idx = tid + (i << 8), row = idx >> 3, q = idx & 7;
        pa[i] = *(const float4*)(arow(row) + (q << 2));
        pb[i] = *(const float4*)(Bbase + (size_t)row * K + (q << 2));
    }
    {
        float* Abuf = smem;
        float* Bbuf = smem + A_FLOATS;
        #pragma unroll
        for (int i = 0; i < 4; ++i) {
            int idx = tid + (i << 8), row = idx >> 3, q = idx & 7;
            uint4 ta, tb;
            ta.x = f2tf32(pa[i].x); ta.y = f2tf32(pa[i].y);
            ta.z = f2tf32(pa[i].z); ta.w = f2tf32(pa[i].w);
            tb.x = f2tf32(pb[i].x); tb.y = f2tf32(pb[i].y);
            tb.z = f2tf32(pb[i].z); tb.w = f2tf32(pb[i].w);
            int soff = row * BK + ((q ^ (row & 7)) << 2);
            *(uint4*)(Abuf + soff) = ta;
            *(uint4*)(Bbuf + soff) = tb;
        }
    }
    __syncthreads();

    for (int it = 0; it < niter; ++it) {
        const int buf = it & 1;
        if (it + 1 < niter) {
            const int ko = (it + 1) * BK;
            #pragma unroll
            for (int i = 0; i < 4; ++i) {
                int idx = tid + (i << 8), row = idx >> 3, q = idx & 7;
                pa[i] = *(const float4*)(arow(row) + ko + (q << 2));
                pb[i] = *(const float4*)(Bbase + (size_t)row * K + ko + (q << 2));
            }
        }
        {
            const uint32_t* Abuf = (const uint32_t*)(smem + buf * BUF_FLOATS);
            const uint32_t* Bbuf = Abuf + A_FLOATS;
            #pragma unroll
            for (int ks = 0; ks < 4; ++ks) {
                uint32_t af[4][4], bf[4][2];
                const int g0 = ((2 * ks) ^ g) << 2;
                const int g1 = ((2 * ks + 1) ^ g) << 2;
                #pragma unroll
                for (int mt = 0; mt < 4; ++mt) {
                    int r0 = wm + mt * 16 + g;
                    int r1 = r0 + 8;
                    af[mt][0] = Abuf[r0 * BK + g0 + tg];
                    af[mt][1] = Abuf[r1 * BK + g0 + tg];
                    af[mt][2] = Abuf[r0 * BK + g1 + tg];
                    af[mt][3] = Abuf[r1 * BK + g1 + tg];
                }
                #pragma unroll
                for (int nt = 0; nt < 4; ++nt) {
                    int n = wn + nt * 8 + g;
                    bf[nt][0] = Bbuf[n * BK + g0 + tg];
                    bf[nt][1] = Bbuf[n * BK + g1 + tg];
                }
                #pragma unroll
                for (int mt = 0; mt < 4; ++mt)
                    #pragma unroll
                    for (int nt = 0; nt < 4; ++nt)
                        mma_tf32(acc[mt][nt], af[mt], bf[nt]);
            }
        }
        if (it + 1 < niter) {
            float* Abuf = smem + (buf ^ 1) * BUF_FLOATS;
            float* Bbuf = Abuf + A_FLOATS;
            #pragma unroll
            for (int i = 0; i < 4; ++i) {
                int idx = tid + (i << 8), row = idx >> 3, q = idx & 7;
                uint4 ta, tb;
                ta.x = f2tf32(pa[i].x); ta.y = f2tf32(pa[i].y);
                ta.z = f2tf32(pa[i].z); ta.w = f2tf32(pa[i].w);
                tb.x = f2tf32(pb[i].x); tb.y = f2tf32(pb[i].y);
                tb.z = f2tf32(pb[i].z); tb.w = f2tf32(pb[i].w);
                int soff = row * BK + ((q ^ (row & 7)) << 2);
                *(uint4*)(Abuf + soff) = ta;
                *(uint4*)(Bbuf + soff) = tb;
            }
            __syncthreads();
        }
    }

    // ---- epilogue: C = acc + bias ----
    #pragma unroll
    for (int mt = 0; mt < 4; ++mt) {
        #pragma unroll
        for (int nt = 0; nt < 4; ++nt) {
            int lr0 = wm + mt * 16 + g;
            int lr1 = lr0 + 8;
            int col = wn + nt * 8 + tg * 2;
            float b0 = bias[colB + col], b1 = bias[colB + col + 1];
            float2 v0 = make_float2(acc[mt][nt][0] + b0, acc[mt][nt][1] + b1);
            float2 v1 = make_float2(acc[mt][nt][2] + b0, acc[mt][nt][3] + b1);
            if (GATHER) {
                if (rowBase + lr0 < nrows)
                    *(float2*)(C + (size_t)ridx_s[lr0] * ldc + colC + col) = v0;
                if (rowBase + lr1 < nrows)
                    *(float2*)(C + (size_t)ridx_s[lr1] * ldc + colC + col) = v1;
            } else {
                *(float2*)(C + (size_t)(rowBase + lr0) * ldc + colC + col) = v0;
                *(float2*)(C + (size_t)(rowBase + lr1) * ldc + colC + col) = v1;
            }
        }
    }
}

// QKV kernel: y 0..3 -> V dense (all rows); y 4..11 -> Q/K gathered (non-reset)
__global__ __launch_bounds__(256) void qkv_gemm_tc(
    const float* __restrict__ x,
    const float* __restrict__ Wq, const float* __restrict__ bq,
    const float* __restrict__ Wk, const float* __restrict__ bk,
    const float* __restrict__ Wv, const float* __restrict__ bv)
{
    const int y = blockIdx.y;
    if (y < 4) {
        // V for ALL rows (reset rows need v_new)
        const int nc = y * BN;
        tc_gemm_body<false>(x, Wv, bv, g_qkv, DIM, QKV_LD,
                            blockIdx.x * BM, nc, 2 * DWM + nc, DIM / BK, BSZ);
    } else {
        const int q  = y - 4;          // 0..7
        const int zz = q >> 2;         // 0=Q, 1=K
        const int nc = (q & 3) * BN;
        const int nrows = g_nrows;
        if (blockIdx.x * BM >= nrows) return;   // inactive tail tile
        const float* Bw = zz ? Wk : Wq;
        const float* bi = zz ? bk : bq;
        tc_gemm_body<true>(x, Bw, bi, g_qkv, DIM, QKV_LD,
                           blockIdx.x * BM, nc, zz * DWM + nc, DIM / BK, nrows);
    }
}

__global__ __launch_bounds__(256) void out_gemm_tc(
    const float* __restrict__ Wo, const float* __restrict__ bo,
    float* __restrict__ y)
{
    tc_gemm_body<false>(g_att, Wo, bo, y, DWM, DIM,
                        blockIdx.x * BM, blockIdx.y * BN, blockIdx.y * BN,
                        DWM / BK, BSZ);
}

// ---------------- Attention kernel: one CTA per batch row --------------------
// Reset rows: only freshly-written slot valid -> out = v_new exactly (early exit).
__global__ __launch_bounds__(256) void attn_kernel(
    const float* __restrict__ wmK, const float* __restrict__ wmV,
    const void* __restrict__ validIn,
    const void* __restrict__ resetIn,
    const int* __restrict__ ptrIn)
{
    __shared__ float q_s[DWM];
    __shared__ float att_s[NH][WIN];
    __shared__ unsigned char valid_s[WIN];

    const int b    = blockIdx.x;
    const int tid  = threadIdx.x;   // 256
    const int lane = tid & 31;
    const int warp = tid >> 5;      // 8 warps == 8 heads

    const int mode = bool_mode((const unsigned char*)validIn);
    const bool rs = read_bool(resetIn, b, mode);

    const float* qrow  = g_qkv + (size_t)b * QKV_LD;
    const float* knew  = qrow + DWM;
    const float* vnew  = qrow + 2 * DWM;

    if (rs) {
        float2 v0 = *(const float2*)(vnew + tid * 2);
        *(float2*)(g_att + (size_t)b * DWM + tid * 2) = v0;
        return;
    }

    const int p = ptrIn[b];
    const float* Kbase = wmK + (size_t)b * WIN * DWM;
    const float* Vbase = wmV + (size_t)b * WIN * DWM;

    for (int i = tid; i < DWM; i += 256) q_s[i] = qrow[i];
    if (tid < WIN)
        valid_s[tid] = read_bool(validIn, (size_t)b * WIN + tid, mode) ? 1 : 0;
    __syncthreads();

    const float NEG_INF = __int_as_float(0xff800000);

    // ---- phase 1: logits (uniform over stored K; slot p patched after) ----
    {
        const int h = warp;
        float2 qv = *(const float2*)(q_s + h * HD + lane * 2);
        const float2* kp = (const float2*)(Kbase + h * HD + lane * 2);
        for (int w0 = 0; w0 < WIN; w0 += 8) {
            float s[8];
            #pragma unroll
            for (int u = 0; u < 8; ++u) {
                float2 kv = __ldcs(kp + (size_t)(w0 + u) * (DWM / 2));
                s[u] = kv.x * qv.x + kv.y * qv.y;
            }
            #pragma unroll
            for (int u = 0; u < 8; ++u) {
                #pragma unroll
                for (int o = 16; o > 0; o >>= 1)
                    s[u] += __shfl_xor_sync(0xffffffffu, s[u], o);
            }
            if (lane == 0) {
                #pragma unroll
                for (int u = 0; u < 8; ++u) {
                    int w = w0 + u;
                    bool val = (valid_s[w] != 0);
                    att_s[h][w] = val ? s[u] * ATT_SCALE : NEG_INF;
                }
            }
        }
        {
            float2 kv = *(const float2*)(knew + h * HD + lane * 2);
            float s = kv.x * qv.x + kv.y * qv.y;
            #pragma unroll
            for (int o = 16; o > 0; o >>= 1)
                s += __shfl_xor_sync(0xffffffffu, s, o);
            if (lane == 0) att_s[h][p] = s * ATT_SCALE;
        }
    }
    __syncthreads();

    // ---- phase 2: per-head softmax (warp h) ----
    {
        const int h = warp;
        float e[8];
        float m = NEG_INF;
        #pragma unroll
        for (int j = 0; j < 8; ++j) {
            e[j] = att_s[h][lane + 32 * j];
            m = fmaxf(m, e[j]);
        }
        #pragma unroll
        for (int o = 16; o > 0; o >>= 1)
            m = fmaxf(m, __shfl_xor_sync(0xffffffffu, m, o));
        float sum = 0.f;
        #pragma unroll
        for (int j = 0; j < 8; ++j) {
            e[j] = __expf(e[j] - m);
            sum += e[j];
        }
        #pragma unroll
        for (int o = 16; o > 0; o >>= 1)
            sum += __shfl_xor_sync(0xffffffffu, sum, o);
        float inv = (sum > 0.f) ? (1.0f / sum) : 0.f;
        #pragma unroll
        for (int j = 0; j < 8; ++j)
            att_s[h][lane + 32 * j] = e[j] * inv;
    }
    __syncthreads();

    // ---- phase 3: AV, uniform over stored V; correction for slot p ----
    {
        const int d = tid * 2;
        const int h = tid >> 5;
        float ax = 0.f, ay = 0.f;
        const float2* vp = (const float2*)(Vbase + d);
        for (int w0 = 0; w0 < WIN; w0 += 8) {
            float2 vv[8];
            #pragma unroll
            for (int u = 0; u < 8; ++u)
                vv[u] = __ldcs(vp + (size_t)(w0 + u) * (DWM / 2));
            #pragma unroll
            for (int u = 0; u < 8; ++u) {
                float pw = att_s[h][w0 + u];
                ax = fmaf(pw, vv[u].x, ax);
                ay = fmaf(pw, vv[u].y, ay);
            }
        }
        {
            float2 vold = *(const float2*)(Vbase + (size_t)p * DWM + d);
            float2 vn   = *(const float2*)(vnew + d);
            float pw = att_s[h][p];
            ax = fmaf(pw, vn.x - vold.x, ax);
            ay = fmaf(pw, vn.y - vold.y, ay);
        }
        *(float2*)(g_att + (size_t)b * DWM + d) = make_float2(ax, ay);
    }
}

// ---------------- launcher ---------------------------------------------------
extern "C" void kernel_launch(void* const* d_in, const int* in_sizes, int n_in,
                              void* d_out, int out_size)
{
    const float* x     = (const float*)d_in[0];
    const void*  reset = d_in[1];
    const float* wmK   = (const float*)d_in[2];
    const float* wmV   = (const float*)d_in[3];
    const void*  valid = d_in[4];
    const int*   ptr   = (const int*)d_in[5];
    const float* Wq    = (const float*)d_in[6];
    const float* bq    = (const float*)d_in[7];
    const float* Wk    = (const float*)d_in[8];
    const float* bk    = (const float*)d_in[9];
    const float* Wv    = (const float*)d_in[10];
    const float* bv    = (const float*)d_in[11];
    const float* Wo    = (const float*)d_in[12];
    const float* bo    = (const float*)d_in[13];
    float*       y     = (float*)d_out;

    // opt-in to 64 KB dynamic smem (host attribute set; idempotent)
    cudaFuncSetAttribute(qkv_gemm_tc, cudaFuncAttributeMaxDynamicSharedMemorySize, TCSM_BYTES);
    cudaFuncSetAttribute(out_gemm_tc, cudaFuncAttributeMaxDynamicSharedMemorySize, TCSM_BYTES);

    compact_kernel<<<1, 1024>>>(reset, valid);

    dim3 gQKV(BSZ / BM, 12);            // 16 x 12; Q/K tail tiles self-disable
    qkv_gemm_tc<<<gQKV, 256, TCSM_BYTES>>>(x, Wq, bq, Wk, bk, Wv, bv);

    attn_kernel<<<BSZ, 256>>>(wmK, wmV, valid, reset, ptr);

    dim3 gOut(BSZ / BM, DIM / BN);      // 16 x 8 = 128 CTAs
    out_gemm_tc<<<gOut, 256, TCSM_BYTES>>>(Wo, bo, y);
}